// round 2
// baseline (speedup 1.0000x reference)
#include <cuda_runtime.h>
#include <math.h>

#define B_    8
#define N_    2048
#define FIN_  128
#define FOUT_ 64
#define BN_   (B_ * N_)

#define TI      128
#define TJ      64
#define JSPLIT  2
#define JCHUNK  (N_ / JSPLIT)

// -------- scratch (device globals; no runtime allocation) --------
__device__ float g_h[BN_ * FOUT_];                 // 4 MB : h = x @ W
__device__ float g_s1[BN_], g_s2[BN_];
__device__ float g_E1[BN_], g_F1[BN_], g_E2[BN_], g_F2[BN_];
__device__ float g_acc[JSPLIT][BN_ * FOUT_];       // 8 MB : partial aggregations
__device__ float g_l[JSPLIT][BN_];                 // partial softmax denominators

// ============================================================================
// Kernel 1: h = x @ W  (per row) + s1 = h.a1, s2 = h.a2 + per-node exps
// grid: BN_/128 blocks, 128 threads (4 f-groups x 32 row-threads, 4 rows/thread)
// ============================================================================
__global__ __launch_bounds__(128) void k1_proj(const float* __restrict__ x,
                                               const float* __restrict__ W,
                                               const float* __restrict__ a) {
    __shared__ float sW[FIN_ * FOUT_];   // 32 KB
    __shared__ float sr1[128 * 4];
    __shared__ float sr2[128 * 4];

    const int t = threadIdx.x;
    {
        float4*       d = reinterpret_cast<float4*>(sW);
        const float4* s = reinterpret_cast<const float4*>(W);
        #pragma unroll
        for (int q = 0; q < 16; ++q) d[t + q * 128] = s[t + q * 128];
    }
    __syncthreads();

    const int fg = t >> 5;       // 0..3 : which 16-col group of FOUT
    const int rt = t & 31;       // row-thread within block
    const int rowbase = blockIdx.x * 128;

    float acc[4][16];
    #pragma unroll
    for (int r = 0; r < 4; ++r)
        #pragma unroll
        for (int c = 0; c < 16; ++c) acc[r][c] = 0.f;

    const float4* x4 = reinterpret_cast<const float4*>(x);
    for (int k4 = 0; k4 < FIN_ / 4; ++k4) {
        float xs[4][4];
        #pragma unroll
        for (int rr = 0; rr < 4; ++rr) {
            float4 xv = x4[(size_t)(rowbase + rt + 32 * rr) * (FIN_ / 4) + k4];
            xs[rr][0] = xv.x; xs[rr][1] = xv.y; xs[rr][2] = xv.z; xs[rr][3] = xv.w;
        }
        #pragma unroll
        for (int q = 0; q < 4; ++q) {
            const int k = k4 * 4 + q;
            const float4* wr = reinterpret_cast<const float4*>(&sW[k * FOUT_ + fg * 16]);
            const float4 w0 = wr[0], w1 = wr[1], w2 = wr[2], w3 = wr[3];
            #pragma unroll
            for (int rr = 0; rr < 4; ++rr) {
                const float xv = xs[rr][q];
                acc[rr][0]  += xv * w0.x; acc[rr][1]  += xv * w0.y;
                acc[rr][2]  += xv * w0.z; acc[rr][3]  += xv * w0.w;
                acc[rr][4]  += xv * w1.x; acc[rr][5]  += xv * w1.y;
                acc[rr][6]  += xv * w1.z; acc[rr][7]  += xv * w1.w;
                acc[rr][8]  += xv * w2.x; acc[rr][9]  += xv * w2.y;
                acc[rr][10] += xv * w2.z; acc[rr][11] += xv * w2.w;
                acc[rr][12] += xv * w3.x; acc[rr][13] += xv * w3.y;
                acc[rr][14] += xv * w3.z; acc[rr][15] += xv * w3.w;
            }
        }
    }

    // epilogue: store h, compute partial dots with a1/a2
    float a1v[16], a2v[16];
    #pragma unroll
    for (int f = 0; f < 16; ++f) {
        a1v[f] = a[fg * 16 + f];
        a2v[f] = a[FOUT_ + fg * 16 + f];
    }
    #pragma unroll
    for (int rr = 0; rr < 4; ++rr) {
        const int rloc = rt + 32 * rr;
        const size_t row = (size_t)rowbase + rloc;
        float4* hd = reinterpret_cast<float4*>(&g_h[row * FOUT_ + fg * 16]);
        #pragma unroll
        for (int f4 = 0; f4 < 4; ++f4)
            hd[f4] = make_float4(acc[rr][f4 * 4], acc[rr][f4 * 4 + 1],
                                 acc[rr][f4 * 4 + 2], acc[rr][f4 * 4 + 3]);
        float ps1 = 0.f, ps2 = 0.f;
        #pragma unroll
        for (int f = 0; f < 16; ++f) {
            ps1 += acc[rr][f] * a1v[f];
            ps2 += acc[rr][f] * a2v[f];
        }
        sr1[rloc * 4 + fg] = ps1;
        sr2[rloc * 4 + fg] = ps2;
    }
    __syncthreads();
    if (t < 128) {
        const int row = rowbase + t;
        const float s1 = sr1[t * 4] + sr1[t * 4 + 1] + sr1[t * 4 + 2] + sr1[t * 4 + 3];
        const float s2 = sr2[t * 4] + sr2[t * 4 + 1] + sr2[t * 4 + 2] + sr2[t * 4 + 3];
        g_s1[row] = s1;
        g_s2[row] = s2;
        g_E1[row] = expf(s1);           // exp(s1)
        g_F1[row] = expf(0.2f * s1);    // exp(alpha*s1)
        g_E2[row] = expf(s2);
        g_F2[row] = expf(0.2f * s2);
    }
}

// ============================================================================
// Kernel 2: fused masked attention + aggregation (no max-subtraction needed:
// scores are O(10), exp is fp32-safe; masked entries contribute exactly 0).
// p_ij = adj ? ((s1+s2>0) ? E1*E2 : F1*F2) : 0        (zero MUFU per pair)
// acc_if += p_ij * h_jf ; l_i += p_ij
// grid: (N/TI, B, JSPLIT), 256 threads, dynamic smem ~50 KB
// ============================================================================
__global__ __launch_bounds__(256) void k2_attn(const int* __restrict__ adj) {
    extern __shared__ float sm[];
    float* smH  = sm;                 // TJ*64   = 4096 floats
    float* smP  = sm + 4096;          // TJ*128  = 8192 floats (XOR-swizzled)
    float* s_s1 = smP + 8192;         // 128
    float* s_E1 = s_s1 + 128;
    float* s_F1 = s_E1 + 128;
    float* s_s2 = s_F1 + 128;         // 64
    float* s_E2 = s_s2 + 64;
    float* s_F2 = s_E2 + 64;

    const int t  = threadIdx.x;
    const int b  = blockIdx.y;
    const int i0 = blockIdx.x * TI;
    const int js = blockIdx.z;
    const int jbase = js * JCHUNK;
    const int nb = b * N_;

    if (t < TI) {
        const int g = nb + i0 + t;
        s_s1[t] = g_s1[g]; s_E1[t] = g_E1[g]; s_F1[t] = g_F1[g];
    }

    const int tf = t >> 5;            // warp id = f-group (8 cols each)
    const int ti = t & 31;            // i-group (4 rows each)
    const int f0 = tf * 8;

    float acc[4][8];
    #pragma unroll
    for (int r = 0; r < 4; ++r)
        #pragma unroll
        for (int c = 0; c < 8; ++c) acc[r][c] = 0.f;
    float lacc[4] = {0.f, 0.f, 0.f, 0.f};

    const int j4  = t & 15;           // phase-A j quad
    const int ibA = t >> 4;           // phase-A i base

    for (int jt = 0; jt < JCHUNK; jt += TJ) {
        const int j0 = jbase + jt;
        __syncthreads();   // previous tile fully consumed
        {   // load h tile [TJ][64]
            const float4* src = reinterpret_cast<const float4*>(&g_h[(size_t)(nb + j0) * FOUT_]);
            float4* dst = reinterpret_cast<float4*>(smH);
            #pragma unroll
            for (int q = 0; q < 4; ++q) dst[t + q * 256] = src[t + q * 256];
        }
        if (t < 64)        s_s2[t]       = g_s2[nb + j0 + t];
        else if (t < 128)  s_E2[t - 64]  = g_E2[nb + j0 + t - 64];
        else if (t < 192)  s_F2[t - 128] = g_F2[nb + j0 + t - 128];
        __syncthreads();

        // ---- Phase A: compute P tile into swizzled smem ----
        #pragma unroll
        for (int ii = 0; ii < 8; ++ii) {
            const int i = ibA + ii * 16;
            const float s1 = s_s1[i], E1 = s_E1[i], F1 = s_F1[i];
            const int4 aj = *reinterpret_cast<const int4*>(
                adj + (size_t)(nb + i0 + i) * N_ + j0 + j4 * 4);
            const int jl = j4 * 4;
            const int av[4] = {aj.x, aj.y, aj.z, aj.w};
            #pragma unroll
            for (int q = 0; q < 4; ++q) {
                const int j = jl + q;
                const float xsum = s1 + s_s2[j];
                float p = (xsum > 0.f) ? (E1 * s_E2[j]) : (F1 * s_F2[j]);
                p = (av[q] > 0) ? p : 0.f;
                smP[j * 128 + (i ^ ((j & 31) << 2))] = p;
            }
        }
        __syncthreads();

        // ---- Phase B: register-tiled GEMM acc += P * H ----
        #pragma unroll 2
        for (int jj = 0; jj < TJ; ++jj) {
            const float4 pv = *reinterpret_cast<const float4*>(
                &smP[jj * 128 + ((ti * 4) ^ ((jj & 31) << 2))]);
            const float4 hA = *reinterpret_cast<const float4*>(&smH[jj * FOUT_ + f0]);
            const float4 hB = *reinterpret_cast<const float4*>(&smH[jj * FOUT_ + f0 + 4]);
            const float pr[4] = {pv.x, pv.y, pv.z, pv.w};
            const float hv[8] = {hA.x, hA.y, hA.z, hA.w, hB.x, hB.y, hB.z, hB.w};
            #pragma unroll
            for (int r = 0; r < 4; ++r)
                #pragma unroll
                for (int c = 0; c < 8; ++c)
                    acc[r][c] += pr[r] * hv[c];
            if (tf == 0) {   // warp-uniform branch: warp 0 carries l
                lacc[0] += pv.x; lacc[1] += pv.y; lacc[2] += pv.z; lacc[3] += pv.w;
            }
        }
    }

    // write partials
    #pragma unroll
    for (int r = 0; r < 4; ++r) {
        const size_t row = (size_t)nb + i0 + ti * 4 + r;
        float4* dst = reinterpret_cast<float4*>(&g_acc[js][row * FOUT_ + f0]);
        dst[0] = make_float4(acc[r][0], acc[r][1], acc[r][2], acc[r][3]);
        dst[1] = make_float4(acc[r][4], acc[r][5], acc[r][6], acc[r][7]);
    }
    if (tf == 0) {
        #pragma unroll
        for (int r = 0; r < 4; ++r)
            g_l[js][nb + i0 + ti * 4 + r] = lacc[r];
    }
}

// ============================================================================
// Kernel 3: combine j-splits, normalize, LayerNorm, ELU.  One warp per row.
// ============================================================================
__global__ __launch_bounds__(256) void k3_ln(const float* __restrict__ gamma,
                                             const float* __restrict__ beta,
                                             float* __restrict__ out) {
    const int t = threadIdx.x;
    const int warp = t >> 5, lane = t & 31;
    const int row = blockIdx.x * 8 + warp;
    const size_t base = (size_t)row * FOUT_;

    const float v0 = g_acc[0][base + lane]      + g_acc[1][base + lane];
    const float v1 = g_acc[0][base + 32 + lane] + g_acc[1][base + 32 + lane];
    const float l  = g_l[0][row] + g_l[1][row];
    const float inv = 1.f / l;
    const float h0 = v0 * inv, h1 = v1 * inv;

    float s = h0 + h1;
    #pragma unroll
    for (int o = 16; o; o >>= 1) s += __shfl_xor_sync(0xffffffffu, s, o);
    const float mu = s * (1.f / 64.f);

    const float d0 = h0 - mu, d1 = h1 - mu;
    float vs = d0 * d0 + d1 * d1;
    #pragma unroll
    for (int o = 16; o; o >>= 1) vs += __shfl_xor_sync(0xffffffffu, vs, o);
    const float rstd = rsqrtf(vs * (1.f / 64.f) + 1e-5f);

    const float y0 = d0 * rstd * gamma[lane]      + beta[lane];
    const float y1 = d1 * rstd * gamma[lane + 32] + beta[lane + 32];
    out[base + lane]      = (y0 > 0.f) ? y0 : expm1f(y0);
    out[base + 32 + lane] = (y1 > 0.f) ? y1 : expm1f(y1);
}

// ============================================================================
extern "C" void kernel_launch(void* const* d_in, const int* in_sizes, int n_in,
                              void* d_out, int out_size) {
    const float* x     = (const float*)d_in[0];
    const int*   adj   = (const int*)  d_in[1];
    const float* W     = (const float*)d_in[2];
    const float* a     = (const float*)d_in[3];
    const float* gamma = (const float*)d_in[4];
    const float* beta  = (const float*)d_in[5];
    float* out = (float*)d_out;

    const int smem2 = (4096 + 8192 + 3 * 128 + 3 * 64) * (int)sizeof(float); // 51456 B
    cudaFuncSetAttribute(k2_attn, cudaFuncAttributeMaxDynamicSharedMemorySize, smem2);

    k1_proj<<<BN_ / 128, 128>>>(x, W, a);
    k2_attn<<<dim3(N_ / TI, B_, JSPLIT), 256, smem2>>>(adj);
    k3_ln<<<BN_ / 8, 256>>>(gamma, beta, out);
}